// round 7
// baseline (speedup 1.0000x reference)
#include <cuda_runtime.h>

// STTEncoder: replicate the reference's fp32 integral image BITWISE.
// jnp.cumsum -> reduce_window -> XLA ReduceWindowRewriter(base=16):
//   recursive blocked-sequential scan:
//     P[r,j]  = seq fold of x[16r..16r+j]            (81 blocks, padded 1296)
//     B[r]    = P[r,15]
//     P2[u,v] = seq fold of B[16u..16u+v]            (6 blocks, padded 96)
//     C[u]    = P2[u,15];  S3 = seq fold of C (6)
//     OFF2[u] = S3[u-1] (0 for u=0)
//     S2[t]   = OFF2[t>>4] + P2[t]                   (one rounded add)
//     OFF[r]  = S2[r-1] (0 for r=0)
//     S[i]    = OFF[i>>4] + P[i>>4, i&15]            (one rounded add)
// ii computed only at the NX needed boundary coords (x==y set by symmetry).

#define IMG_W 1280
#define TS 16
constexpr int NTOK = 172;
constexpr int N1 = IMG_W + 1;   // padded scan length (1281)
constexpr int NB1 = 81;         // ceil(1281/16)
constexpr int NB1P = 96;        // padded to 6*16
constexpr int NB2 = 6;

struct Tok { int x, y, s; };
struct Table { Tok t[NTOK]; int count; };

constexpr Table make_table() {
    Table tb{};
    constexpr int STR[5] = {1, 2, 4, 6, 8};
    constexpr int GRD[5] = {4, 4, 6, 8, 10};
    int n = 0;
    int plo = 0, phi = 0;
    bool has = false;
    for (int sc = 0; sc < 5; ++sc) {
        int s = STR[sc], g = GRD[sc];
        int cov = g * TS * s;
        int off = (IMG_W - cov) / 2;
        for (int j = 0; j < g; ++j)
            for (int i = 0; i < g; ++i) {
                int x = off + i * TS * s;
                int y = off + j * TS * s;
                if (has && x >= plo && x + TS * s <= phi &&
                    y >= plo && y + TS * s <= phi)
                    continue;
                tb.t[n].x = x; tb.t[n].y = y; tb.t[n].s = s; ++n;
            }
        plo = off; phi = off + cov; has = true;
    }
    tb.count = n;
    return tb;
}
static_assert(make_table().count == NTOK, "token count mismatch");
__constant__ Table TOKS = make_table();

// ---- needed boundary coordinate set (same for x and y) ----
struct BMask { bool m[N1]; };
constexpr BMask make_bmask() {
    BMask b{};
    Table tb = make_table();
    for (int t = 0; t < NTOK; ++t) {
        int s = tb.t[t].s;
        for (int i = 0; i <= TS; ++i) {
            b.m[tb.t[t].x + s * i] = true;
            b.m[tb.t[t].y + s * i] = true;
        }
    }
    return b;
}
constexpr int count_bounds() {
    BMask b = make_bmask(); int c = 0;
    for (int i = 0; i < N1; ++i) if (b.m[i]) ++c;
    return c;
}
constexpr int NX = count_bounds();
static_assert(NX <= 512, "boundary set too large");
constexpr int NXPAD = (NX + 3) / 4 * 4;

struct BMapT { short cmap[N1]; short list[NX]; };
constexpr BMapT make_bmap() {
    BMapT r{};
    BMask b = make_bmask();
    int c = 0;
    for (int i = 0; i < N1; ++i) {
        if (b.m[i]) { r.cmap[i] = (short)c; r.list[c] = (short)i; ++c; }
        else r.cmap[i] = -1;
    }
    return r;
}
__device__ const BMapT BMAP = make_bmap();

// ---- scratch (device globals: no allocation allowed) ----
__device__ float g_Sx[48ull * IMG_W * NXPAD];   // [bc][y][xc]: x-scan at needed cols
__device__ float g_ii[48ull * NX * NXPAD];      // [bc][yc][xc]: ii at needed (y,x)

// ======================= Stage 1: x-scan per image row =======================
__global__ __launch_bounds__(128) void stt_stage1(const float* __restrict__ img) {
    __shared__ float sx[N1];       // padded row; becomes per-block prefixes P
    __shared__ float b2[NB1P];     // block sums B; becomes level-2 prefixes P2
    __shared__ float off2[NB2];    // exclusive level-2 offsets
    const int y  = blockIdx.x;
    const int bc = blockIdx.y;
    const int tid = threadIdx.x;

    const float* row = img + ((size_t)bc * IMG_W + y) * IMG_W;
    if (tid == 0) sx[0] = 0.f;                 // leading pad zero
    for (int i = tid; i < IMG_W; i += 128) sx[1 + i] = row[i];
    __syncthreads();

    // level 1: sequential fold within 16-blocks (in place)
    if (tid < NB1P) {
        if (tid < NB1) {
            const int base = tid * 16;
            const int lim  = (base + 16 <= N1) ? 16 : (N1 - base);
            float acc = 0.f;
            for (int j = 0; j < lim; ++j) { acc = acc + sx[base + j]; sx[base + j] = acc; }
            b2[tid] = acc;
        } else {
            b2[tid] = 0.f;                     // zero padding of block sums
        }
    }
    __syncthreads();

    // level 2: sequential fold of block sums within 16-blocks (in place)
    if (tid < NB2) {
        const int base = tid * 16;
        float acc = 0.f;
        for (int v = 0; v < 16; ++v) { acc = acc + b2[base + v]; b2[base + v] = acc; }
    }
    __syncthreads();

    // level 3: sequential fold of 6 level-2 totals -> exclusive offsets
    if (tid == 0) {
        float acc = 0.f;
        off2[0] = 0.f;
        for (int u = 0; u < NB2 - 1; ++u) { acc = acc + b2[u * 16 + 15]; off2[u + 1] = acc; }
    }
    __syncthreads();

    // sample at needed columns: S[i] = (OFF2 + P2) + P   (exact add orders)
    float* dst = g_Sx + ((size_t)bc * IMG_W + y) * NXPAD;
    for (int xi = tid; xi < NX; xi += 128) {
        const int i = BMAP.list[xi];
        const int r = i >> 4;
        float v = sx[i];
        if (r) v = (off2[(r - 1) >> 4] + b2[r - 1]) + v;
        dst[xi] = v;
    }
}

// ============== Stage 2: y-scan per needed column (warp/column) =============
__global__ __launch_bounds__(128) void stt_stage2() {
    __shared__ float sy[4][N1 + 3];
    __shared__ float b2s[4][NB1P];
    __shared__ float off2s[4][NB2];
    const int bc   = blockIdx.y;
    const int w    = threadIdx.x >> 5;       // warp -> column slot
    const int lane = threadIdx.x & 31;
    const int xc   = blockIdx.x * 4 + w;

    float* sy_c = sy[w];
    float* b2_c = b2s[w];
    float* off2_c = off2s[w];

    if (lane == 0) sy_c[0] = 0.f;            // padded y=0 row of ii is zero
    const float* src = g_Sx + (size_t)bc * IMG_W * NXPAD + xc;
    for (int y = lane; y < IMG_W; y += 32)
        sy_c[1 + y] = src[(size_t)y * NXPAD];
    __syncwarp();

    // level 1
    for (int r = lane; r < NB1P; r += 32) {
        if (r < NB1) {
            const int base = r * 16;
            const int lim  = (base + 16 <= N1) ? 16 : (N1 - base);
            float acc = 0.f;
            for (int j = 0; j < lim; ++j) { acc = acc + sy_c[base + j]; sy_c[base + j] = acc; }
            b2_c[r] = acc;
        } else {
            b2_c[r] = 0.f;
        }
    }
    __syncwarp();

    // level 2
    if (lane < NB2) {
        const int base = lane * 16;
        float acc = 0.f;
        for (int v = 0; v < 16; ++v) { acc = acc + b2_c[base + v]; b2_c[base + v] = acc; }
    }
    __syncwarp();

    // level 3
    if (lane == 0) {
        float acc = 0.f;
        off2_c[0] = 0.f;
        for (int u = 0; u < NB2 - 1; ++u) { acc = acc + b2_c[u * 16 + 15]; off2_c[u + 1] = acc; }
    }
    __syncwarp();

    float* dst = g_ii + (size_t)bc * NX * NXPAD + xc;
    for (int yi = lane; yi < NX; yi += 32) {
        const int i = BMAP.list[yi];
        const int r = i >> 4;
        float v = sy_c[i];
        if (r) v = (off2_c[(r - 1) >> 4] + b2_c[r - 1]) + v;
        dst[(size_t)yi * NXPAD] = v;
    }
}

// ===================== Stage 3: 4-corner gather + divide =====================
__global__ __launch_bounds__(256) void stt_stage3(float* __restrict__ out) {
    const int tok = blockIdx.x;
    const int bc  = blockIdx.y;
    const Tok t = TOKS.t[tok];
    const int tx = threadIdx.x, ty = threadIdx.y;

    const int xl = t.x + t.s * tx, xu = xl + t.s;
    const int yl = t.y + t.s * ty, yu = yl + t.s;
    const int cxl = BMAP.cmap[xl], cxu = BMAP.cmap[xu];
    const int cyl = BMAP.cmap[yl], cyu = BMAP.cmap[yu];

    const float* ii = g_ii + (size_t)bc * NX * NXPAD;
    const float A = ii[cyu * NXPAD + cxu];
    const float B = ii[cyu * NXPAD + cxl];
    const float C = ii[cyl * NXPAD + cxu];
    const float D = ii[cyl * NXPAD + cxl];
    // reference op order: ii[yu,xu] - ii[yu,xl] - ii[yl,xu] + ii[yl,xl]
    const float box = ((A - B) - C) + D;

    const int b = bc / 3, ch = bc % 3;
    const size_t o = ((((size_t)b * NTOK + tok) * 3 + ch) * TS + ty) * TS + tx;
    out[o] = box / (float)(t.s * t.s);
}

extern "C" void kernel_launch(void* const* d_in, const int* in_sizes, int n_in,
                              void* d_out, int out_size) {
    const float* img = (const float*)d_in[0];
    float* out = (float*)d_out;

    dim3 g1(IMG_W, 48);            // one block per (row, bc)
    stt_stage1<<<g1, 128>>>(img);

    dim3 g2(NXPAD / 4, 48);        // 4 needed columns per block (warp each)
    stt_stage2<<<g2, 128>>>();

    dim3 g3(NTOK, 48);
    stt_stage3<<<g3, dim3(TS, TS)>>>(out);
}

// round 8
// speedup vs baseline: 3.6134x; 3.6134x over previous
#include <cuda_runtime.h>

// STTEncoder: replicate the reference's fp32 integral image bitwise.
// jnp.cumsum -> reduce_window -> XLA ReduceWindowRewriter(base=16):
// blocked-sequential recursive scan (verified PASS in R7, rel_err 1.6e-8).
//   S[i] = r==0 ? P[0,i] : (off2[(r-1)>>4] + b2[r-1]) + P[r, i&15]
// This round: register folds + conflict-free smem (stage1), coalesced
// tiled column scan with register state (stage2).

#define IMG_W 1280
#define TS 16
constexpr int NTOK = 172;
constexpr int N1 = IMG_W + 1;   // padded scan length (1281)
constexpr int NB1 = 81;         // ceil(1281/16)
constexpr int NB1P = 96;        // padded to 6*16
constexpr int NB2 = 6;

struct Tok { int x, y, s; };
struct Table { Tok t[NTOK]; int count; };

constexpr Table make_table() {
    Table tb{};
    constexpr int STR[5] = {1, 2, 4, 6, 8};
    constexpr int GRD[5] = {4, 4, 6, 8, 10};
    int n = 0;
    int plo = 0, phi = 0;
    bool has = false;
    for (int sc = 0; sc < 5; ++sc) {
        int s = STR[sc], g = GRD[sc];
        int cov = g * TS * s;
        int off = (IMG_W - cov) / 2;
        for (int j = 0; j < g; ++j)
            for (int i = 0; i < g; ++i) {
                int x = off + i * TS * s;
                int y = off + j * TS * s;
                if (has && x >= plo && x + TS * s <= phi &&
                    y >= plo && y + TS * s <= phi)
                    continue;
                tb.t[n].x = x; tb.t[n].y = y; tb.t[n].s = s; ++n;
            }
        plo = off; phi = off + cov; has = true;
    }
    tb.count = n;
    return tb;
}
static_assert(make_table().count == NTOK, "token count mismatch");
__constant__ Table TOKS = make_table();

// ---- needed boundary coordinate set (same for x and y) ----
struct BMask { bool m[N1]; };
constexpr BMask make_bmask() {
    BMask b{};
    Table tb = make_table();
    for (int t = 0; t < NTOK; ++t) {
        int s = tb.t[t].s;
        for (int i = 0; i <= TS; ++i) {
            b.m[tb.t[t].x + s * i] = true;
            b.m[tb.t[t].y + s * i] = true;
        }
    }
    return b;
}
constexpr int count_bounds() {
    BMask b = make_bmask(); int c = 0;
    for (int i = 0; i < N1; ++i) if (b.m[i]) ++c;
    return c;
}
constexpr int NX = count_bounds();
static_assert(NX <= 512, "boundary set too large");
constexpr int NX32 = (NX + 31) / 32 * 32;   // padded row width (also col-group count*32)

struct BMapT { short cmap[N1]; };
constexpr BMapT make_bmap() {
    BMapT r{};
    BMask b = make_bmask();
    int c = 0;
    for (int i = 0; i < N1; ++i) {
        if (b.m[i]) { r.cmap[i] = (short)c; ++c; }
        else r.cmap[i] = -1;
    }
    return r;
}
__device__ const BMapT BMAP = make_bmap();

// per-16-block needed-position mask + cumulative output base
struct BlkInfo { unsigned short mask; short base; };
struct BlkTab { BlkInfo b[NB1]; int total; };
constexpr BlkTab make_blk() {
    BlkTab t{};
    BMask m = make_bmask();
    int cnt = 0;
    for (int r = 0; r < NB1; ++r) {
        t.b[r].base = (short)cnt;
        unsigned short msk = 0;
        for (int j = 0; j < 16; ++j) {
            int i = r * 16 + j;
            if (i < N1 && m.m[i]) { msk |= (unsigned short)(1u << j); ++cnt; }
        }
        t.b[r].mask = msk;
    }
    t.total = cnt;
    return t;
}
static_assert(make_blk().total == NX, "mask/base table inconsistent");
__device__ const BlkTab BLK = make_blk();

// ---- scratch (device globals: no allocation allowed) ----
__device__ float g_Sx[48ull * IMG_W * NX32];   // [bc][y][xc]: x-prefix at needed cols
__device__ float g_ii[48ull * NX * NX32];      // [bc][yc][xc]: ii at needed (y,x)

// ======================= Stage 1: x-scan per image row =======================
// thread r owns padded 16-block [16r,16r+16). Aligned float4 loads cover cols
// [16r,16r+16); the block's first element (col 16r-1) comes from neighbor via smem.
__global__ __launch_bounds__(96) void stt_stage1(const float* __restrict__ img) {
    __shared__ float s_last[80];     // col 16r+15, feeds block r+1's first element
    __shared__ float s_bsum[NB1P];   // block sums -> level-2 prefixes (in place)
    __shared__ float s_off2[NB2];    // exclusive level-2 offsets
    const int y  = blockIdx.x;
    const int bc = blockIdx.y;
    const int r  = threadIdx.x;      // 0..95

    float v[16];
    if (r < 80) {
        const float4* p4 = reinterpret_cast<const float4*>(
            img + ((size_t)bc * IMG_W + y) * IMG_W + r * 16);
        float4 a = p4[0], b = p4[1], c = p4[2], d = p4[3];
        v[0]=a.x; v[1]=a.y; v[2]=a.z; v[3]=a.w;
        v[4]=b.x; v[5]=b.y; v[6]=b.z; v[7]=b.w;
        v[8]=c.x; v[9]=c.y; v[10]=c.z; v[11]=c.w;
        v[12]=d.x; v[13]=d.y; v[14]=d.z; v[15]=d.w;
        s_last[r] = v[15];
    }
    __syncthreads();

    float p[16];
    if (r < NB1) {
        // e0 = x[16r] = (r==0 ? pad 0 : col 16r-1); acc = 0 + e0 (exact)
        float acc = 0.f + ((r == 0) ? 0.f : s_last[r - 1]);
        p[0] = acc;
        if (r < 80) {
#pragma unroll
            for (int j = 1; j < 16; ++j) { acc = acc + v[j - 1]; p[j] = acc; }
        }
        s_bsum[r] = acc;             // block sum (r=80: single-element block)
    } else {
        s_bsum[r] = 0.f;             // padded block sums (81..95)
    }
    __syncthreads();

    // level 2: sequential prefix within 16-groups of block sums (in place)
    if (r < NB2) {
        const int base = r * 16;
        float acc = 0.f;
#pragma unroll
        for (int u = 0; u < 16; ++u) { acc = acc + s_bsum[base + u]; s_bsum[base + u] = acc; }
    }
    __syncthreads();

    // level 3: exclusive fold of group totals
    if (r == 0) {
        float acc = 0.f;
        s_off2[0] = 0.f;
#pragma unroll
        for (int u = 0; u < NB2 - 1; ++u) { acc = acc + s_bsum[u * 16 + 15]; s_off2[u + 1] = acc; }
    }
    __syncthreads();

    // sampled writes: S[i] = (off2 + b2prefix) + P  (exact add order)
    if (r < NB1) {
        const BlkInfo bi = BLK.b[r];
        if (bi.mask) {
            float* dst = g_Sx + ((size_t)bc * IMG_W + y) * NX32 + bi.base;
            float add = 0.f;
            if (r > 0) add = s_off2[(r - 1) >> 4] + s_bsum[r - 1];
            int o = 0;
#pragma unroll
            for (int j = 0; j < 16; ++j)
                if ((bi.mask >> j) & 1)
                    dst[o++] = r ? (add + p[j]) : p[j];
        }
    }
}

// ============ Stage 2: y-scan, 32 columns/block, tiled + coalesced ===========
__global__ __launch_bounds__(128) void stt_stage2() {
    __shared__ float tile[2][16][33];     // [buf][row-in-block][col], stride 33: conflict-free
    const int c0 = blockIdx.x * 32;
    const int bc = blockIdx.y;
    const int t  = threadIdx.x;
    const int jr = t >> 5, c = t & 31;    // loader: 4 rows x 32 cols per pass

    const float* src = g_Sx + (size_t)bc * IMG_W * NX32 + c0;
    float* dstc = g_ii + (size_t)bc * NX * NX32 + c0 + c;

    // load tile for y-block r into buffer bufi (padded i=16r+j -> image row i-1)
    auto load_tile = [&](int r, int bufi) {
#pragma unroll
        for (int k = 0; k < 4; ++k) {
            const int j = jr + k * 4;
            const int yy = r * 16 + j - 1;
            tile[bufi][j][c] = (yy >= 0 && yy < IMG_W) ? src[(size_t)yy * NX32 + c] : 0.f;
        }
    };

    load_tile(0, 0);
    __syncthreads();

    // per-lane scan state for column c0+c (exact XLA fold orders)
    float acc2 = 0.f;      // b2prefix[r-1] at block entry
    float off_cur = 0.f;   // off2[current group]

    for (int r = 0; r < NB1; ++r) {
        if (r + 1 < NB1) load_tile(r + 1, (r + 1) & 1);
        if (t < 32) {
            float off_used = off_cur;
            if (r > 0 && (r & 15) == 0) {          // entering group u: need off2[u-1]
                off_cur = off_cur + acc2;          // off2[u] = off2[u-1] + total[u-1]
            }
            const float add = off_used + acc2;     // off2[(r-1)>>4] + b2prefix[r-1]
            const BlkInfo bi = BLK.b[r];
            float p = 0.f;
            int o = bi.base;
#pragma unroll
            for (int j = 0; j < 16; ++j) {
                p = p + tile[r & 1][j][c];
                if ((bi.mask >> j) & 1) {
                    dstc[(size_t)o * NX32] = r ? (add + p) : p;
                    ++o;
                }
            }
            acc2 = ((r & 15) == 0) ? p : (acc2 + p);   // b2prefix[r]
        }
        __syncthreads();
    }
}

// ===================== Stage 3: 4-corner gather + divide =====================
__global__ __launch_bounds__(256) void stt_stage3(float* __restrict__ out) {
    const int tok = blockIdx.x;
    const int bc  = blockIdx.y;
    const Tok t = TOKS.t[tok];
    const int tx = threadIdx.x, ty = threadIdx.y;

    const int xl = t.x + t.s * tx, xu = xl + t.s;
    const int yl = t.y + t.s * ty, yu = yl + t.s;
    const int cxl = BMAP.cmap[xl], cxu = BMAP.cmap[xu];
    const int cyl = BMAP.cmap[yl], cyu = BMAP.cmap[yu];

    const float* ii = g_ii + (size_t)bc * NX * NX32;
    const float A = ii[cyu * NX32 + cxu];
    const float B = ii[cyu * NX32 + cxl];
    const float C = ii[cyl * NX32 + cxu];
    const float D = ii[cyl * NX32 + cxl];
    const float box = ((A - B) - C) + D;   // reference op order

    const int b = bc / 3, ch = bc % 3;
    const size_t o = ((((size_t)b * NTOK + tok) * 3 + ch) * TS + ty) * TS + tx;
    out[o] = box / (float)(t.s * t.s);
}

extern "C" void kernel_launch(void* const* d_in, const int* in_sizes, int n_in,
                              void* d_out, int out_size) {
    const float* img = (const float*)d_in[0];
    float* out = (float*)d_out;

    dim3 g1(IMG_W, 48);
    stt_stage1<<<g1, 96>>>(img);

    dim3 g2(NX32 / 32, 48);
    stt_stage2<<<g2, 128>>>();

    dim3 g3(NTOK, 48);
    stt_stage3<<<g3, dim3(TS, TS)>>>(out);
}

// round 9
// speedup vs baseline: 4.4867x; 1.2417x over previous
#include <cuda_runtime.h>

// STTEncoder: replicate the reference's fp32 integral image bitwise.
// jnp.cumsum -> reduce_window -> XLA ReduceWindowRewriter(base=16):
// blocked-sequential recursive scan (PASS since R7, rel_err 1.6e-8).
//   S[i] = r==0 ? P[0,i] : (off2[(r-1)>>4] + b2[r-1]) + P[r, i&15]
// R9: stage1 coalesced loads via 17-pitch smem transpose + coalesced
// compacted writes; stage2 cp.async 4-deep pipeline.

#define IMG_W 1280
#define TS 16
constexpr int NTOK = 172;
constexpr int N1 = IMG_W + 1;   // padded scan length (1281)
constexpr int NB1 = 81;         // ceil(1281/16)
constexpr int NB1P = 96;        // padded to 6*16
constexpr int NB2 = 6;

struct Tok { int x, y, s; };
struct Table { Tok t[NTOK]; int count; };

constexpr Table make_table() {
    Table tb{};
    constexpr int STR[5] = {1, 2, 4, 6, 8};
    constexpr int GRD[5] = {4, 4, 6, 8, 10};
    int n = 0;
    int plo = 0, phi = 0;
    bool has = false;
    for (int sc = 0; sc < 5; ++sc) {
        int s = STR[sc], g = GRD[sc];
        int cov = g * TS * s;
        int off = (IMG_W - cov) / 2;
        for (int j = 0; j < g; ++j)
            for (int i = 0; i < g; ++i) {
                int x = off + i * TS * s;
                int y = off + j * TS * s;
                if (has && x >= plo && x + TS * s <= phi &&
                    y >= plo && y + TS * s <= phi)
                    continue;
                tb.t[n].x = x; tb.t[n].y = y; tb.t[n].s = s; ++n;
            }
        plo = off; phi = off + cov; has = true;
    }
    tb.count = n;
    return tb;
}
static_assert(make_table().count == NTOK, "token count mismatch");
__constant__ Table TOKS = make_table();

// ---- needed boundary coordinate set (same for x and y) ----
struct BMask { bool m[N1]; };
constexpr BMask make_bmask() {
    BMask b{};
    Table tb = make_table();
    for (int t = 0; t < NTOK; ++t) {
        int s = tb.t[t].s;
        for (int i = 0; i <= TS; ++i) {
            b.m[tb.t[t].x + s * i] = true;
            b.m[tb.t[t].y + s * i] = true;
        }
    }
    return b;
}
constexpr int count_bounds() {
    BMask b = make_bmask(); int c = 0;
    for (int i = 0; i < N1; ++i) if (b.m[i]) ++c;
    return c;
}
constexpr int NX = count_bounds();
static_assert(NX <= 512, "boundary set too large");
constexpr int NX32 = (NX + 31) / 32 * 32;

struct BMapT { short cmap[N1]; };
constexpr BMapT make_bmap() {
    BMapT r{};
    BMask b = make_bmask();
    int c = 0;
    for (int i = 0; i < N1; ++i) {
        if (b.m[i]) { r.cmap[i] = (short)c; ++c; }
        else r.cmap[i] = -1;
    }
    return r;
}
__device__ const BMapT BMAP = make_bmap();

// per-16-block needed-position mask + cumulative output base
struct BlkInfo { unsigned short mask; short base; };
struct BlkTab { BlkInfo b[NB1]; int total; };
constexpr BlkTab make_blk() {
    BlkTab t{};
    BMask m = make_bmask();
    int cnt = 0;
    for (int r = 0; r < NB1; ++r) {
        t.b[r].base = (short)cnt;
        unsigned short msk = 0;
        for (int j = 0; j < 16; ++j) {
            int i = r * 16 + j;
            if (i < N1 && m.m[i]) { msk |= (unsigned short)(1u << j); ++cnt; }
        }
        t.b[r].mask = msk;
    }
    t.total = cnt;
    return t;
}
static_assert(make_blk().total == NX, "mask/base table inconsistent");
__device__ const BlkTab BLK = make_blk();

// ---- scratch (device globals: no allocation allowed) ----
__device__ float g_Sx[48ull * IMG_W * NX32];   // [bc][y][xc]
__device__ float g_ii[48ull * NX * NX32];      // [bc][yc][xc]

// ======================= Stage 1: x-scan per image row =======================
// Coalesced float4 loads -> smem with 17-float group pitch (fold reads at
// 17r+j are bank-conflict-free). Fold per 16-block in registers; sampled
// values compacted in smem and written coalesced.
__global__ __launch_bounds__(128) void stt_stage1(const float* __restrict__ img) {
    __shared__ float srow[80 * 17];   // pixel q at 17*(q/16) + q%16
    __shared__ float s_bsum[NB1P];
    __shared__ float s_off2[NB2];
    __shared__ float s_out[NX];       // compacted sampled prefix values
    const int y  = blockIdx.x;
    const int bc = blockIdx.y;
    const int t  = threadIdx.x;       // 0..127

    const float4* src4 = reinterpret_cast<const float4*>(
        img + ((size_t)bc * IMG_W + y) * IMG_W);
#pragma unroll
    for (int k = 0; k < 3; ++k) {     // 320 float4s
        const int j = t + k * 128;
        if (j < 320) {
            float4 v = src4[j];        // coalesced: lanes 16B apart
            float* d = &srow[17 * (j >> 2) + 4 * (j & 3)];
            d[0] = v.x; d[1] = v.y; d[2] = v.z; d[3] = v.w;
        }
    }
    __syncthreads();

    // level 1: sequential fold of padded block r = elements [16r,16r+16)
    //   element 16r+j = (16r+j==0 ? 0 : pixel[16r+j-1])
    float p[16];
    if (t < NB1) {
        const int r = t;
        float acc = 0.f + ((r == 0) ? 0.f : srow[17 * r - 2]);  // pixel 16r-1
        p[0] = acc;
        if (r < 80) {
            const float* q = &srow[17 * r];   // pixels 16r..16r+14
#pragma unroll
            for (int j = 1; j < 16; ++j) { acc = acc + q[j - 1]; p[j] = acc; }
        }
        s_bsum[r] = acc;
    } else if (t < NB1P) {
        s_bsum[t] = 0.f;               // padded block sums
    }
    __syncthreads();

    // level 2: sequential prefix within 16-groups of block sums (in place)
    if (t < NB2) {
        const int base = t * 16;
        float acc = 0.f;
#pragma unroll
        for (int u = 0; u < 16; ++u) { acc = acc + s_bsum[base + u]; s_bsum[base + u] = acc; }
    }
    __syncthreads();

    // level 3: exclusive fold of group totals
    if (t == 0) {
        float acc = 0.f;
        s_off2[0] = 0.f;
#pragma unroll
        for (int u = 0; u < NB2 - 1; ++u) { acc = acc + s_bsum[u * 16 + 15]; s_off2[u + 1] = acc; }
    }
    __syncthreads();

    // sampled values into compact smem: S[i] = (off2 + b2prefix) + P
    if (t < NB1) {
        const int r = t;
        const BlkInfo bi = BLK.b[r];
        if (bi.mask) {
            float add = 0.f;
            if (r > 0) add = s_off2[(r - 1) >> 4] + s_bsum[r - 1];
            int o = bi.base;
#pragma unroll
            for (int j = 0; j < 16; ++j)
                if ((bi.mask >> j) & 1) { s_out[o] = r ? (add + p[j]) : p[j]; ++o; }
        }
    }
    __syncthreads();

    float* dst = g_Sx + ((size_t)bc * IMG_W + y) * NX32;
    for (int i = t; i < NX; i += 128) dst[i] = s_out[i];    // coalesced
}

// ============ Stage 2: y-scan, 32 cols/block, cp.async 4-deep pipeline ======
__global__ __launch_bounds__(128) void stt_stage2() {
    __shared__ float tile[4][16][33];     // stride-33 rows: conflict-free
    const int c0 = blockIdx.x * 32;
    const int bc = blockIdx.y;
    const int t  = threadIdx.x;
    const int jr = t >> 5, c = t & 31;    // loaders: 4 rows x 32 cols/pass

    const float* src = g_Sx + (size_t)bc * IMG_W * NX32 + c0;
    float* dstc = g_ii + (size_t)bc * NX * NX32 + c0 + c;

    auto issue = [&](int r) {
#pragma unroll
        for (int k = 0; k < 4; ++k) {
            const int j = jr + k * 4;
            const int yy = r * 16 + j - 1;
            const bool ok = (yy >= 0) && (yy < IMG_W);
            const int yc = ok ? yy : 0;
            const float* g = src + (size_t)yc * NX32 + c;
            unsigned saddr = (unsigned)__cvta_generic_to_shared(&tile[r & 3][j][c]);
            int sz = ok ? 4 : 0;       // src-size 0 -> zero-fill
            asm volatile("cp.async.ca.shared.global [%0], [%1], 4, %2;\n"
                         :: "r"(saddr), "l"(g), "r"(sz));
        }
        asm volatile("cp.async.commit_group;\n" ::: "memory");
    };

    issue(0); issue(1); issue(2);

    // per-lane scan state for column c0+c (exact XLA fold orders; == R8)
    float acc2 = 0.f;      // b2prefix[r-1] at block entry
    float off_cur = 0.f;   // off2[current group]

    for (int r = 0; r < NB1; ++r) {
        asm volatile("cp.async.wait_group 2;\n" ::: "memory");
        __syncthreads();
        if (r + 3 < NB1) issue(r + 3);
        else asm volatile("cp.async.commit_group;\n" ::: "memory");
        if (t < 32) {
            float off_used = off_cur;
            if (r > 0 && (r & 15) == 0)
                off_cur = off_cur + acc2;          // off2[u] = off2[u-1] + total[u-1]
            const float add = off_used + acc2;     // off2[(r-1)>>4] + b2prefix[r-1]
            const BlkInfo bi = BLK.b[r];
            float p = 0.f;
            int o = bi.base;
#pragma unroll
            for (int j = 0; j < 16; ++j) {
                p = p + tile[r & 3][j][c];
                if ((bi.mask >> j) & 1) {
                    dstc[(size_t)o * NX32] = r ? (add + p) : p;
                    ++o;
                }
            }
            acc2 = ((r & 15) == 0) ? p : (acc2 + p);   // b2prefix[r]
        }
    }
}

// ===================== Stage 3: 4-corner gather + divide =====================
__global__ __launch_bounds__(256) void stt_stage3(float* __restrict__ out) {
    const int tok = blockIdx.x;
    const int bc  = blockIdx.y;
    const Tok t = TOKS.t[tok];
    const int tx = threadIdx.x, ty = threadIdx.y;

    const int xl = t.x + t.s * tx, xu = xl + t.s;
    const int yl = t.y + t.s * ty, yu = yl + t.s;
    const int cxl = BMAP.cmap[xl], cxu = BMAP.cmap[xu];
    const int cyl = BMAP.cmap[yl], cyu = BMAP.cmap[yu];

    const float* ii = g_ii + (size_t)bc * NX * NX32;
    const float A = ii[cyu * NX32 + cxu];
    const float B = ii[cyu * NX32 + cxl];
    const float C = ii[cyl * NX32 + cxu];
    const float D = ii[cyl * NX32 + cxl];
    const float box = ((A - B) - C) + D;   // reference op order

    const int b = bc / 3, ch = bc % 3;
    const size_t o = ((((size_t)b * NTOK + tok) * 3 + ch) * TS + ty) * TS + tx;
    out[o] = box / (float)(t.s * t.s);
}

extern "C" void kernel_launch(void* const* d_in, const int* in_sizes, int n_in,
                              void* d_out, int out_size) {
    const float* img = (const float*)d_in[0];
    float* out = (float*)d_out;

    dim3 g1(IMG_W, 48);
    stt_stage1<<<g1, 128>>>(img);

    dim3 g2(NX32 / 32, 48);
    stt_stage2<<<g2, 128>>>();

    dim3 g3(NTOK, 48);
    stt_stage3<<<g3, dim3(TS, TS)>>>(out);
}